// round 3
// baseline (speedup 1.0000x reference)
#include <cuda_runtime.h>

// Fixed problem shapes
#define BB 64
#define CC 64   // C == Co
#define TT 32
#define NN 64
#define KK 3

#define STRIDE 68               // 64 + 4 pad: float4-aligned, bank-spread rows
#define BUF (64 * STRIDE)
#define SMEM_FLOATS (4 * BUF + 2 * 64)
#define SMEM_BYTES  (SMEM_FLOATS * 4)

// W transposed once into device-global scratch (WT[c][o] = W[o][c])
__device__ float g_WT[CC * CC];

__global__ void wt_transpose_kernel(const float* __restrict__ W)
{
    const int i = blockIdx.x * 256 + threadIdx.x;   // 0..4095
    const int o = i >> 6;
    const int c = i & 63;
    g_WT[c * CC + o] = W[i];
}

// One CTA per (b, t-pair). 256 threads = 2 graph-groups of 128.
// Per graph: 16x8 thread grid, each thread an 8-row x 4-col register tile.
// Buffers: sX[g]: x tile -> yT tile ; sW: WT -> Asum(g0) ; sE: Asum(g1)
__global__ void __launch_bounds__(256, 3)
ctg_kernel(const float* __restrict__ x,
           const float* __restrict__ A,
           const float* __restrict__ bias,
           float* __restrict__ out,
           int copyA)
{
    extern __shared__ float sm[];
    float* sX0   = sm;                 // x(g0) -> yT(g0)
    float* sX1   = sm + BUF;           // x(g1) -> yT(g1)
    float* sW    = sm + 2 * BUF;       // WT -> Asum(g0)
    float* sE    = sm + 3 * BUF;       // Asum(g1)
    float* sDinv = sm + 4 * BUF;       // [2][64]

    const int tid = threadIdx.x;
    const int b   = blockIdx.x >> 4;
    const int t0  = (blockIdx.x & 15) * 2;

    const int g   = tid >> 7;          // graph within CTA
    const int lt  = tid & 127;         // lane within graph-group
    const int tx  = lt & 15;           // 4-col group (m/o)
    const int ty  = lt >> 4;           // 8-row group (rows 8ty..8ty+7)
    const int t   = t0 + g;

    float* sXg = g ? sX1 : sX0;
    float* sAg = g ? sE  : sW;
    float* sDg = sDinv + g * 64;

    // ---- stage x (both graphs) and WT ----
    #pragma unroll
    for (int it = 0; it < 8; it++) {
        const int e4 = it * 256 + tid;      // 0..2047
        const int gg = e4 >> 10;
        const int sl = e4 & 1023;
        const int r  = sl >> 4;
        const int c4 = sl & 15;
        float* dst = (gg ? sX1 : sX0) + r * STRIDE + c4 * 4;
        *(float4*)dst = *(const float4*)(x + (((size_t)(b * CC + r) * TT + (t0 + gg)) * NN) + c4 * 4);
    }
    #pragma unroll
    for (int it = 0; it < 4; it++) {
        const int e4 = it * 256 + tid;      // 0..1023
        const int r  = e4 >> 4;
        const int c4 = e4 & 15;
        *(float4*)(sW + r * STRIDE + c4 * 4) = *(const float4*)(g_WT + (size_t)e4 * 4);
    }
    __syncthreads();

    // ---- GEMM1: yT[n][o] = sum_c x[c][n] * WT[c][o] + bias[o] ----
    float acc[8][4];
    #pragma unroll
    for (int i = 0; i < 8; i++)
        #pragma unroll
        for (int j = 0; j < 4; j++) acc[i][j] = 0.0f;

    #pragma unroll 4
    for (int kk = 0; kk < 64; kk++) {
        const float4 a0 = *(const float4*)(sXg + kk * STRIDE + ty * 8);     // x[kk][8ty..]
        const float4 a1 = *(const float4*)(sXg + kk * STRIDE + ty * 8 + 4);
        const float4 bv = *(const float4*)(sW  + kk * STRIDE + tx * 4);     // WT[kk][4tx..]
        const float av[8] = {a0.x, a0.y, a0.z, a0.w, a1.x, a1.y, a1.z, a1.w};
        #pragma unroll
        for (int i = 0; i < 8; i++) {
            acc[i][0] += av[i] * bv.x;
            acc[i][1] += av[i] * bv.y;
            acc[i][2] += av[i] * bv.z;
            acc[i][3] += av[i] * bv.w;
        }
    }
    __syncthreads();   // all x/WT reads complete before overwriting

    {
        const float4 bia = *(const float4*)(bias + tx * 4);
        #pragma unroll
        for (int i = 0; i < 8; i++) {
            float4 r4;
            r4.x = acc[i][0] + bia.x;
            r4.y = acc[i][1] + bia.y;
            r4.z = acc[i][2] + bia.z;
            r4.w = acc[i][3] + bia.w;
            *(float4*)(sXg + (8 * ty + i) * STRIDE + tx * 4) = r4;   // yT[n][o]
        }
    }

    // ---- A-phase: register A_k + register Asum, shfl degrees ----
    float* outA = out + (size_t)BB * CC * TT * NN;

    float4 asum[8];
    #pragma unroll
    for (int it = 0; it < 8; it++) { asum[it].x = asum[it].y = asum[it].z = asum[it].w = 0.0f; }

    const int m0 = tx * 4;

    for (int k = 0; k < KK; k++) {
        const size_t base = (((size_t)b * KK + k) * TT + t) * (size_t)(NN * NN);

        float4 a[8];
        #pragma unroll
        for (int it = 0; it < 8; it++) {
            const int e4 = it * 128 + lt;   // this graph's 1024 float4 slots
            a[it] = *(const float4*)(A + base + (size_t)e4 * 4);
            if (copyA) *(float4*)(outA + base + (size_t)e4 * 4) = a[it];
        }

        // row degrees: 16 consecutive lanes (same lt>>4) hold one row per it
        #pragma unroll
        for (int it = 0; it < 8; it++) {
            float s = a[it].x + a[it].y + a[it].z + a[it].w;
            s += __shfl_xor_sync(0xffffffffu, s, 1);
            s += __shfl_xor_sync(0xffffffffu, s, 2);
            s += __shfl_xor_sync(0xffffffffu, s, 4);
            s += __shfl_xor_sync(0xffffffffu, s, 8);
            if (tx == 0) sDg[it * 8 + ty] = rsqrtf(s + 1.0f);   // A_tilde = A + I
        }
        __syncthreads();

        const float4 dm = *(const float4*)(sDg + m0);
        #pragma unroll
        for (int it = 0; it < 8; it++) {
            const int n = it * 8 + ty;
            const float dn = sDg[n];
            float4 v = a[it];
            const int d = n - m0;
            if (d == 0) v.x += 1.0f;
            if (d == 1) v.y += 1.0f;
            if (d == 2) v.z += 1.0f;
            if (d == 3) v.w += 1.0f;
            asum[it].x += v.x * dn * dm.x;
            asum[it].y += v.y * dn * dm.y;
            asum[it].z += v.z * dn * dm.z;
            asum[it].w += v.w * dn * dm.w;
        }
        __syncthreads();   // protect sDinv before next k
    }

    // Asum -> smem (WT/spare buffers are dead)
    #pragma unroll
    for (int it = 0; it < 8; it++)
        *(float4*)(sAg + (it * 8 + ty) * STRIDE + m0) = asum[it];
    __syncthreads();

    // ---- GEMM2: x_out[c][m] = sum_n yT[n][c] * Asum[n][m] ----
    #pragma unroll
    for (int i = 0; i < 8; i++)
        #pragma unroll
        for (int j = 0; j < 4; j++) acc[i][j] = 0.0f;

    #pragma unroll 4
    for (int kk = 0; kk < 64; kk++) {
        const float4 a0 = *(const float4*)(sXg + kk * STRIDE + ty * 8);     // yT[kk][8ty..]
        const float4 a1 = *(const float4*)(sXg + kk * STRIDE + ty * 8 + 4);
        const float4 bv = *(const float4*)(sAg + kk * STRIDE + tx * 4);     // Asum[kk][4tx..]
        const float av[8] = {a0.x, a0.y, a0.z, a0.w, a1.x, a1.y, a1.z, a1.w};
        #pragma unroll
        for (int i = 0; i < 8; i++) {
            acc[i][0] += av[i] * bv.x;
            acc[i][1] += av[i] * bv.y;
            acc[i][2] += av[i] * bv.z;
            acc[i][3] += av[i] * bv.w;
        }
    }

    #pragma unroll
    for (int i = 0; i < 8; i++) {
        const int c = 8 * ty + i;
        float4 r4;
        r4.x = acc[i][0]; r4.y = acc[i][1]; r4.z = acc[i][2]; r4.w = acc[i][3];
        *(float4*)(out + (((size_t)(b * CC + c) * TT + t) * NN) + m0) = r4;
    }
}

extern "C" void kernel_launch(void* const* d_in, const int* in_sizes, int n_in,
                              void* d_out, int out_size)
{
    const float* x    = (const float*)d_in[0];
    const float* A    = (const float*)d_in[1];
    const float* W    = (const float*)d_in[2];
    const float* bias = (const float*)d_in[3];
    float* out = (float*)d_out;

    const int xout_elems = BB * CC * TT * NN;           // 8,388,608
    const int copyA = (out_size > xout_elems) ? 1 : 0;  // tuple output (x_out, A)

    wt_transpose_kernel<<<16, 256>>>(W);

    cudaFuncSetAttribute(ctg_kernel, cudaFuncAttributeMaxDynamicSharedMemorySize, SMEM_BYTES);
    ctg_kernel<<<BB * (TT / 2), 256, SMEM_BYTES>>>(x, A, bias, out, copyA);
}

// round 4
// speedup vs baseline: 1.1728x; 1.1728x over previous
#include <cuda_runtime.h>

// Fixed problem shapes
#define BB 64
#define CC 64   // C == Co
#define TT 32
#define NN 64
#define KK 3

#define STRIDE 68               // 64 + 4 pad: float4-aligned, bank-spread rows
#define BUF (64 * STRIDE)
#define SMEM_FLOATS (2 * BUF + 3 * 64)
#define SMEM_BYTES  (SMEM_FLOATS * 4)     // 35,584 B -> 5+ CTAs/SM

// W transposed once into device-global scratch (WT[c][o] = W[o][c])
__device__ float g_WT[CC * CC];

__global__ void wt_transpose_kernel(const float* __restrict__ W)
{
    const int i = blockIdx.x * 256 + threadIdx.x;   // 0..4095
    const int o = i >> 6;
    const int c = i & 63;
    g_WT[c * CC + o] = W[i];
}

// One CTA per (b, t). 256 threads, 4x4 register tiles, 2 aliased smem buffers.
// s0: x tile [c][n]  -> Asum [n][m]
// s1: WT tile [c][o] -> yT tile [n][o]
// sD: dinv, 3 slabs of 64 (one per k -> no trailing barrier per k)
__global__ void __launch_bounds__(256, 5)
ctg_kernel(const float* __restrict__ x,
           const float* __restrict__ A,
           const float* __restrict__ bias,
           float* __restrict__ out,
           int copyA)
{
    extern __shared__ float sm[];
    float* s0 = sm;
    float* s1 = sm + BUF;
    float* sD = sm + 2 * BUF;

    const int tid = threadIdx.x;
    const int b   = blockIdx.x / TT;
    const int t   = blockIdx.x % TT;
    const int tx  = tid & 15;   // 4-col group
    const int ty  = tid >> 4;   // 4-row group

    // ---- stage x[b,:,t,:] ([c][n]) and WT ([c][o]) via float4 ----
    #pragma unroll
    for (int it = 0; it < 4; it++) {
        const int e4 = it * 256 + tid;    // float4 slot 0..1023
        const int r  = e4 >> 4;
        const int c4 = e4 & 15;
        *(float4*)(s0 + r * STRIDE + c4 * 4) =
            *(const float4*)(x + (((size_t)(b * CC + r) * TT + t) * NN) + c4 * 4);
        *(float4*)(s1 + r * STRIDE + c4 * 4) =
            *(const float4*)(g_WT + (size_t)e4 * 4);
    }
    __syncthreads();

    // ---- GEMM1: yT[n][o] = sum_c x[c][n] * WT[c][o] + bias[o] ----
    float acc[4][4];
    #pragma unroll
    for (int i = 0; i < 4; i++)
        #pragma unroll
        for (int j = 0; j < 4; j++) acc[i][j] = 0.0f;

    #pragma unroll 8
    for (int kk = 0; kk < 64; kk++) {
        const float4 av = *(const float4*)(s0 + kk * STRIDE + ty * 4); // x[kk][4ty..] (broadcast)
        const float4 bv = *(const float4*)(s1 + kk * STRIDE + tx * 4); // WT[kk][4tx..]
        const float a0 = av.x, a1 = av.y, a2 = av.z, a3 = av.w;
        acc[0][0] += a0 * bv.x; acc[0][1] += a0 * bv.y; acc[0][2] += a0 * bv.z; acc[0][3] += a0 * bv.w;
        acc[1][0] += a1 * bv.x; acc[1][1] += a1 * bv.y; acc[1][2] += a1 * bv.z; acc[1][3] += a1 * bv.w;
        acc[2][0] += a2 * bv.x; acc[2][1] += a2 * bv.y; acc[2][2] += a2 * bv.z; acc[2][3] += a2 * bv.w;
        acc[3][0] += a3 * bv.x; acc[3][1] += a3 * bv.y; acc[3][2] += a3 * bv.z; acc[3][3] += a3 * bv.w;
    }
    __syncthreads();   // all x/WT reads done before overwriting s1 with yT

    {
        const float4 bia = *(const float4*)(bias + tx * 4);
        #pragma unroll
        for (int i = 0; i < 4; i++) {
            float4 r4;
            r4.x = acc[i][0] + bia.x;
            r4.y = acc[i][1] + bia.y;
            r4.z = acc[i][2] + bia.z;
            r4.w = acc[i][3] + bia.w;
            *(float4*)(s1 + (4 * ty + i) * STRIDE + tx * 4) = r4;   // yT[n][o]
        }
    }

    // ---- A-phase: register A_k + register Asum, shfl row degrees ----
    float* outA = out + (size_t)BB * CC * TT * NN;

    float4 asum[4];
    #pragma unroll
    for (int it = 0; it < 4; it++) { asum[it].x = asum[it].y = asum[it].z = asum[it].w = 0.0f; }

    const int m0 = tx * 4;

    #pragma unroll
    for (int k = 0; k < KK; k++) {
        const size_t base = (((size_t)b * KK + k) * TT + t) * (size_t)(NN * NN);
        float* sDk = sD + k * 64;

        float4 a[4];
        #pragma unroll
        for (int it = 0; it < 4; it++) {
            const int e4 = it * 256 + tid;
            a[it] = *(const float4*)(A + base + (size_t)e4 * 4);
            if (copyA) *(float4*)(outA + base + (size_t)e4 * 4) = a[it];
        }

        // row degrees: each half-warp holds one full row per it (row = it*16 + ty)
        #pragma unroll
        for (int it = 0; it < 4; it++) {
            float s = a[it].x + a[it].y + a[it].z + a[it].w;
            s += __shfl_xor_sync(0xffffffffu, s, 1);
            s += __shfl_xor_sync(0xffffffffu, s, 2);
            s += __shfl_xor_sync(0xffffffffu, s, 4);
            s += __shfl_xor_sync(0xffffffffu, s, 8);
            if (tx == 0) sDk[it * 16 + ty] = rsqrtf(s + 1.0f);   // A_tilde = A + I
        }
        __syncthreads();

        const float4 dm = *(const float4*)(sDk + m0);
        #pragma unroll
        for (int it = 0; it < 4; it++) {
            const int n = it * 16 + ty;
            const float dn = sDk[n];
            float4 v = a[it];
            const int d = n - m0;
            if (d == 0) v.x += 1.0f;
            if (d == 1) v.y += 1.0f;
            if (d == 2) v.z += 1.0f;
            if (d == 3) v.w += 1.0f;
            asum[it].x += v.x * dn * dm.x;
            asum[it].y += v.y * dn * dm.y;
            asum[it].z += v.z * dn * dm.z;
            asum[it].w += v.w * dn * dm.w;
        }
        // no trailing sync: next k writes a different sD slab
    }

    // Asum -> s0 (x is dead since post-GEMM1 barrier)
    #pragma unroll
    for (int it = 0; it < 4; it++)
        *(float4*)(s0 + (it * 16 + ty) * STRIDE + m0) = asum[it];
    __syncthreads();

    // ---- GEMM2: x_out[c][m] = sum_n yT[n][c] * Asum[n][m] ----
    #pragma unroll
    for (int i = 0; i < 4; i++)
        #pragma unroll
        for (int j = 0; j < 4; j++) acc[i][j] = 0.0f;

    #pragma unroll 8
    for (int kk = 0; kk < 64; kk++) {
        const float4 av = *(const float4*)(s1 + kk * STRIDE + ty * 4); // yT[kk][4ty..] (broadcast)
        const float4 bv = *(const float4*)(s0 + kk * STRIDE + tx * 4); // Asum[kk][4tx..]
        const float a0 = av.x, a1 = av.y, a2 = av.z, a3 = av.w;
        acc[0][0] += a0 * bv.x; acc[0][1] += a0 * bv.y; acc[0][2] += a0 * bv.z; acc[0][3] += a0 * bv.w;
        acc[1][0] += a1 * bv.x; acc[1][1] += a1 * bv.y; acc[1][2] += a1 * bv.z; acc[1][3] += a1 * bv.w;
        acc[2][0] += a2 * bv.x; acc[2][1] += a2 * bv.y; acc[2][2] += a2 * bv.z; acc[2][3] += a2 * bv.w;
        acc[3][0] += a3 * bv.x; acc[3][1] += a3 * bv.y; acc[3][2] += a3 * bv.z; acc[3][3] += a3 * bv.w;
    }

    #pragma unroll
    for (int i = 0; i < 4; i++) {
        const int c = 4 * ty + i;
        float4 r4;
        r4.x = acc[i][0]; r4.y = acc[i][1]; r4.z = acc[i][2]; r4.w = acc[i][3];
        *(float4*)(out + (((size_t)(b * CC + c) * TT + t) * NN) + m0) = r4;
    }
}

extern "C" void kernel_launch(void* const* d_in, const int* in_sizes, int n_in,
                              void* d_out, int out_size)
{
    const float* x    = (const float*)d_in[0];
    const float* A    = (const float*)d_in[1];
    const float* W    = (const float*)d_in[2];
    const float* bias = (const float*)d_in[3];
    float* out = (float*)d_out;

    const int xout_elems = BB * CC * TT * NN;           // 8,388,608
    const int copyA = (out_size > xout_elems) ? 1 : 0;  // tuple output (x_out, A)

    wt_transpose_kernel<<<16, 256>>>(W);

    cudaFuncSetAttribute(ctg_kernel, cudaFuncAttributeMaxDynamicSharedMemorySize, SMEM_BYTES);
    ctg_kernel<<<BB * TT, 256, SMEM_BYTES>>>(x, A, bias, out, copyA);
}